// round 15
// baseline (speedup 1.0000x reference)
#include <cuda_runtime.h>
#include <stdint.h>

// winner[s] = (largest sample index p that writes slot s) + 1, or 0 if none.
// Zero-initialized at module load; rs_gather_kernel resets consumed entries
// to 0, so every kernel_launch call (and graph replay) starts clean.
#define N_SLOTS 16384
#define D_DIM   256
#define ROW_F4  (D_DIM / 4)   // 64 float4 per row

__device__ int g_winner[N_SLOTS];

// K1: each sample p computes its target slot and atomicMax's (p+1) in.
// 4 samples per thread via float4 loads of u.
__global__ void rs_scatter_kernel(const float4* __restrict__ u4,
                                  const int* __restrict__ i0_ptr,
                                  int b, int n) {
    int t = blockIdx.x * blockDim.x + threadIdx.x;
    int p0 = t * 4;
    if (p0 >= b) return;
    int i0 = *i0_ptr;
    float4 uv = u4[t];
    float uu[4] = {uv.x, uv.y, uv.z, uv.w};
#pragma unroll
    for (int k = 0; k < 4; k++) {
        int p = p0 + k;
        int pos = i0 + p;
        int idx;
        if (pos < n) {
            idx = pos;                     // deterministic fill phase
        } else {
            // match JAX exactly: floor(u * float(pos+1)) in f32, clamp to pos
            float prod = uu[k] * (float)(pos + 1);
            int r = (int)floorf(prod);
            idx = r < pos ? r : pos;
        }
        if (idx < n) {
            atomicMax(&g_winner[idx], p + 1);
        }
    }
}

// K2: gather winning rows (or keep old buffer row) into the output, and
// reset consumed winner slots to 0 for the next replay.
// One warp per 4 rows; no shared memory, no barriers:
//   - lanes 0..3 load the 4 winners in one coalesced LDG
//   - __shfl_sync broadcasts them to the warp
//   - the warp issues all 8 float4 loads (2 per row) back-to-back -> MLP=8
//   - lanes 0..3 reset their slot (per-thread load->store same addr ordered)
__global__ void __launch_bounds__(256)
rs_gather_kernel(const float4* __restrict__ samples,
                 const float4* __restrict__ buffer,
                 float4* __restrict__ out) {
    int warp_id = (blockIdx.x * blockDim.x + threadIdx.x) >> 5;
    int lane    = threadIdx.x & 31;
    int s0      = warp_id * 4;          // first of 4 rows owned by this warp

    // lanes 0..3 fetch winners for rows s0..s0+3
    int w_mine = 0;
    if (lane < 4) w_mine = g_winner[s0 + lane];

    int w[4];
#pragma unroll
    for (int r = 0; r < 4; r++)
        w[r] = __shfl_sync(0xFFFFFFFFu, w_mine, r);

    // reset consumed slots (ordered after this thread's own load)
    if (lane < 4 && w_mine != 0) g_winner[s0 + lane] = 0;

    // compute source pointers and issue all 8 loads before any store
    const float4* src[4];
#pragma unroll
    for (int r = 0; r < 4; r++) {
        src[r] = (w[r] > 0) ? (samples + (size_t)(w[r] - 1) * ROW_F4)
                            : (buffer  + (size_t)(s0 + r) * ROW_F4);
    }

    float4 v[8];
#pragma unroll
    for (int r = 0; r < 4; r++) {
        v[2 * r]     = src[r][lane];
        v[2 * r + 1] = src[r][lane + 32];
    }

#pragma unroll
    for (int r = 0; r < 4; r++) {
        float4* o = out + (size_t)(s0 + r) * ROW_F4;
        o[lane]      = v[2 * r];
        o[lane + 32] = v[2 * r + 1];
    }
}

extern "C" void kernel_launch(void* const* d_in, const int* in_sizes, int n_in,
                              void* d_out, int out_size) {
    const float* samples = (const float*)d_in[0];   // [B, 256]
    const float* buffer  = (const float*)d_in[1];   // [N, 256]
    const float* u       = (const float*)d_in[2];   // [B]
    const int*   i0      = (const int*)d_in[3];     // scalar

    int b = in_sizes[2];                // B from u's element count
    int n = in_sizes[1] / D_DIM;        // N from buffer element count

    // K1: scatter sample indices (p+1) with atomicMax; 4 samples/thread
    int threads1 = (b + 3) / 4;
    rs_scatter_kernel<<<(threads1 + 255) / 256, 256>>>(
        (const float4*)u, i0, b, n);

    // K2: one warp per 4 rows -> n/4 warps -> n*8 threads
    rs_gather_kernel<<<(n * 8) / 256, 256>>>(
        (const float4*)samples, (const float4*)buffer, (float4*)d_out);
}

// round 16
// speedup vs baseline: 1.0030x; 1.0030x over previous
#include <cuda_runtime.h>
#include <stdint.h>

// winner[s] = (largest sample index p that writes slot s) + 1, or 0 if none.
// Zero-initialized at module load; rs_gather_kernel resets consumed entries
// to 0, so every kernel_launch call (and graph replay) starts clean.
#define N_SLOTS 16384
#define D_DIM   256
#define ROW_F4  (D_DIM / 4)   // 64 float4 per row

__device__ int g_winner[N_SLOTS];

// K1: each sample p computes its target slot and atomicMax's (p+1) in.
// 4 samples per thread via float4 loads of u.
__global__ void rs_scatter_kernel(const float4* __restrict__ u4,
                                  const int* __restrict__ i0_ptr,
                                  int b, int n) {
    int t = blockIdx.x * blockDim.x + threadIdx.x;
    int p0 = t * 4;
    if (p0 >= b) return;
    int i0 = *i0_ptr;
    float4 uv = u4[t];
    float uu[4] = {uv.x, uv.y, uv.z, uv.w};
#pragma unroll
    for (int k = 0; k < 4; k++) {
        int p = p0 + k;
        int pos = i0 + p;
        int idx;
        if (pos < n) {
            idx = pos;                     // deterministic fill phase
        } else {
            // match JAX exactly: floor(u * float(pos+1)) in f32, clamp to pos
            float prod = uu[k] * (float)(pos + 1);
            int r = (int)floorf(prod);
            idx = r < pos ? r : pos;
        }
        if (idx < n) {
            atomicMax(&g_winner[idx], p + 1);
        }
    }
}

// K2: gather winning rows (or keep old buffer row) into the output, and
// reset consumed winner slots to 0 for the next replay.
// One warp per 4 rows; no shared memory, no barriers:
//   - lanes 0..3 load the 4 winners in one coalesced LDG
//   - __shfl_sync broadcasts them to the warp
//   - the warp issues all 8 float4 loads (2 per row) back-to-back -> MLP=8
//   - lanes 0..3 reset their slot (per-thread load->store same addr ordered)
__global__ void __launch_bounds__(256)
rs_gather_kernel(const float4* __restrict__ samples,
                 const float4* __restrict__ buffer,
                 float4* __restrict__ out) {
    int warp_id = (blockIdx.x * blockDim.x + threadIdx.x) >> 5;
    int lane    = threadIdx.x & 31;
    int s0      = warp_id * 4;          // first of 4 rows owned by this warp

    // lanes 0..3 fetch winners for rows s0..s0+3
    int w_mine = 0;
    if (lane < 4) w_mine = g_winner[s0 + lane];

    int w[4];
#pragma unroll
    for (int r = 0; r < 4; r++)
        w[r] = __shfl_sync(0xFFFFFFFFu, w_mine, r);

    // reset consumed slots (ordered after this thread's own load)
    if (lane < 4 && w_mine != 0) g_winner[s0 + lane] = 0;

    // compute source pointers and issue all 8 loads before any store
    const float4* src[4];
#pragma unroll
    for (int r = 0; r < 4; r++) {
        src[r] = (w[r] > 0) ? (samples + (size_t)(w[r] - 1) * ROW_F4)
                            : (buffer  + (size_t)(s0 + r) * ROW_F4);
    }

    float4 v[8];
#pragma unroll
    for (int r = 0; r < 4; r++) {
        v[2 * r]     = src[r][lane];
        v[2 * r + 1] = src[r][lane + 32];
    }

#pragma unroll
    for (int r = 0; r < 4; r++) {
        float4* o = out + (size_t)(s0 + r) * ROW_F4;
        o[lane]      = v[2 * r];
        o[lane + 32] = v[2 * r + 1];
    }
}

extern "C" void kernel_launch(void* const* d_in, const int* in_sizes, int n_in,
                              void* d_out, int out_size) {
    const float* samples = (const float*)d_in[0];   // [B, 256]
    const float* buffer  = (const float*)d_in[1];   // [N, 256]
    const float* u       = (const float*)d_in[2];   // [B]
    const int*   i0      = (const int*)d_in[3];     // scalar

    int b = in_sizes[2];                // B from u's element count
    int n = in_sizes[1] / D_DIM;        // N from buffer element count

    // K1: scatter sample indices (p+1) with atomicMax; 4 samples/thread
    int threads1 = (b + 3) / 4;
    rs_scatter_kernel<<<(threads1 + 255) / 256, 256>>>(
        (const float4*)u, i0, b, n);

    // K2: one warp per 4 rows -> n/4 warps -> n*8 threads
    rs_gather_kernel<<<(n * 8) / 256, 256>>>(
        (const float4*)samples, (const float4*)buffer, (float4*)d_out);
}